// round 5
// baseline (speedup 1.0000x reference)
#include <cuda_runtime.h>
#include <math.h>

// Clockwork RNN, hierarchically decomposed.
// B=128, T=512, I=2, H=1024, NM=8, MS=128.
// Round 5: split G GEMMs into per-target-block pieces; only the piece needed
// by the next chain stays on the critical path (stream0); all other pieces +
// per-module fc partials run on a second stream overlapped with the chains.

#define NB   128
#define NT   512
#define NH   1024
#define NMOD 8
#define MSZ  128

__constant__ int c_TOFF[8] = {0, 513, 770, 899, 964, 997, 1014, 1023};
__constant__ long long c_GOFF[8] = {0, 0, 4210688, 8437760, 11632640,
                                    13795328, 15187968, 16072704};

__device__ float g_traj[16842752];   // 1028 states * 128 b * 128
__device__ float g_G[16646144];      // per-module context GEMM outputs
__device__ float g_pout[1028 * NB * 2];

// packed f32x2 helpers ------------------------------------------------------
__device__ __forceinline__ void fma2(unsigned long long& d,
                                     unsigned long long a,
                                     unsigned long long b) {
    asm("fma.rn.f32x2 %0, %1, %2, %0;" : "+l"(d) : "l"(a), "l"(b));
}
__device__ __forceinline__ unsigned long long add2(unsigned long long a,
                                                   unsigned long long b) {
    unsigned long long d;
    asm("add.rn.f32x2 %0, %1, %2;" : "=l"(d) : "l"(a), "l"(b));
    return d;
}
union U4 { float4 f; unsigned long long u[2]; };
union U2 { unsigned long long u; float2 f; };

__device__ __forceinline__ float fast_tanh(float v) {
    float e = __expf(2.f * v);
    return 1.f - __fdividef(2.f, e + 1.f);
}

// ---------------------------------------------------------------------------
// Sequential diagonal chain for module M. One CTA per batch element.
// ---------------------------------------------------------------------------
template <int M>
__global__ __launch_bounds__(MSZ, 1) void chain_kernel(
    const float* __restrict__ x,
    const float* __restrict__ W_ih,
    const float* __restrict__ W_hh,
    const float* __restrict__ enc_w) {
    const int b = blockIdx.x;
    const int r = threadIdx.x;
    const int mbase = M * MSZ;
    __shared__ float h_s[2][MSZ];

    unsigned long long Wp[MSZ / 2];
#pragma unroll
    for (int c4 = 0; c4 < MSZ / 4; c4++) {
        U4 w;
        w.f = *(const float4*)(W_hh + (size_t)(mbase + r) * NH + mbase +
                               c4 * 4);
        Wp[2 * c4 + 0] = w.u[0];
        Wp[2 * c4 + 1] = w.u[1];
    }
    const float wih0 = W_ih[(mbase + r) * 2 + 0];
    const float wih1 = W_ih[(mbase + r) * 2 + 1];

    const float x00 = x[(size_t)b * (NT + 1) * 2 + 0];
    const float x01 = x[(size_t)b * (NT + 1) * 2 + 1];
    const float h0v = x00 * enc_w[(mbase + r) * 2 + 0] +
                      x01 * enc_w[(mbase + r) * 2 + 1];
    const size_t tbase = ((size_t)c_TOFF[M] * NB + b) * MSZ;
    h_s[0][r] = h0v;
    g_traj[tbase + r] = h0v;
    __syncthreads();

    const int K = NT >> M;

    float xn0 = x[((size_t)b * (NT + 1) + 1) * 2 + 0];
    float xn1 = x[((size_t)b * (NT + 1) + 1) * 2 + 1];
    float gg[8];
#pragma unroll
    for (int mp = M + 1; mp < NMOD; mp++)
        gg[mp - M - 1] =
            g_G[c_GOFF[mp] + (size_t)b * (mp * MSZ) + mbase + r];

    int p = 0;
    for (int k = 0; k < K; k++) {
        float gsum = xn0 * wih0 + xn1 * wih1;
#pragma unroll
        for (int mp = M + 1; mp < NMOD; mp++) gsum += gg[mp - M - 1];

        float xt0 = 0.f, xt1 = 0.f, gt[8];
        if (k + 1 < K) {
            const int t2 = (k + 1) << M;
            xt0 = x[((size_t)b * (NT + 1) + (t2 + 1)) * 2 + 0];
            xt1 = x[((size_t)b * (NT + 1) + (t2 + 1)) * 2 + 1];
#pragma unroll
            for (int mp = M + 1; mp < NMOD; mp++) {
                const int s = ((t2 - 1) >> mp) + 1;
                gt[mp - M - 1] = g_G[c_GOFF[mp] +
                                     (size_t)(s * NB + b) * (mp * MSZ) +
                                     mbase + r];
            }
        }

        unsigned long long acc[8] = {0, 0, 0, 0, 0, 0, 0, 0};
        const float4* h4 = (const float4*)h_s[p];
#pragma unroll
        for (int c4 = 0; c4 < MSZ / 4; c4++) {
            U4 hv;
            hv.f = h4[c4];
            fma2(acc[(2 * c4) & 7], Wp[2 * c4], hv.u[0]);
            fma2(acc[(2 * c4 + 1) & 7], Wp[2 * c4 + 1], hv.u[1]);
        }
        acc[0] = add2(acc[0], acc[1]);
        acc[2] = add2(acc[2], acc[3]);
        acc[4] = add2(acc[4], acc[5]);
        acc[6] = add2(acc[6], acc[7]);
        acc[0] = add2(acc[0], acc[2]);
        acc[4] = add2(acc[4], acc[6]);
        acc[0] = add2(acc[0], acc[4]);
        U2 a;
        a.u = acc[0];
        const float hn = fast_tanh(a.f.x + a.f.y + gsum);

        h_s[p ^ 1][r] = hn;
        g_traj[tbase + (size_t)(k + 1) * (NB * MSZ) + r] = hn;
        __syncthreads();
        p ^= 1;

        xn0 = xt0; xn1 = xt1;
#pragma unroll
        for (int mp = M + 1; mp < NMOD; mp++) gg[mp - M - 1] = gt[mp - M - 1];
    }
}

// ---------------------------------------------------------------------------
// One target-block piece of G_{mp}:
//   C[:, Mtgt-block] = Traj_{mp} (S*128 x 128) @ W_hh[Mtgt-block rows, mp-cols]^T
// 64x64 tile, 256 threads, 4x4 packed-f32x2 micro-tile, 2 CTAs/SM.
// ---------------------------------------------------------------------------
__global__ __launch_bounds__(256, 2) void g_piece(const float* __restrict__ W_hh,
                                                  int mp, int Mtgt) {
    __shared__ float As[2][64][20];
    __shared__ float Bs[2][64][20];
    const int N = mp * MSZ;
    const float* A = g_traj + (size_t)c_TOFF[mp] * (NB * MSZ);
    float* C = g_G + c_GOFF[mp] + Mtgt * MSZ;
    const int row0 = blockIdx.x * 64;
    const int n0 = blockIdx.y * 64;   // within this 128-col block
    const int tid = threadIdx.x;
    const int tx = tid & 15;
    const int ty = tid >> 4;

    const int lrow = tid >> 2, lc4 = tid & 3;

    const float* Ap = A + (size_t)(row0 + lrow) * MSZ + lc4 * 4;
    const float* Bp = W_hh + (size_t)(Mtgt * MSZ + n0 + lrow) * NH + mp * MSZ +
                      lc4 * 4;

    float4 pa = *(const float4*)Ap;
    float4 pb = *(const float4*)Bp;
    *(float4*)&As[0][lrow][lc4 * 4] = pa;
    *(float4*)&Bs[0][lrow][lc4 * 4] = pb;
    __syncthreads();

    unsigned long long acc[4][4];
#pragma unroll
    for (int i = 0; i < 4; i++)
#pragma unroll
        for (int j = 0; j < 4; j++) acc[i][j] = 0ull;

#pragma unroll
    for (int c = 0; c < 8; c++) {
        const int buf = c & 1;
        if (c < 7) {
            pa = *(const float4*)(Ap + (c + 1) * 16);
            pb = *(const float4*)(Bp + (c + 1) * 16);
        }
#pragma unroll
        for (int k4 = 0; k4 < 4; k4++) {
            U4 af[4], bf[4];
#pragma unroll
            for (int i = 0; i < 4; i++)
                af[i].f = *(const float4*)&As[buf][ty * 4 + i][k4 * 4];
#pragma unroll
            for (int j = 0; j < 4; j++)
                bf[j].f = *(const float4*)&Bs[buf][tx + j * 16][k4 * 4];
#pragma unroll
            for (int i = 0; i < 4; i++)
#pragma unroll
                for (int j = 0; j < 4; j++) {
                    fma2(acc[i][j], af[i].u[0], bf[j].u[0]);
                    fma2(acc[i][j], af[i].u[1], bf[j].u[1]);
                }
        }
        if (c < 7) {
            const int nb = buf ^ 1;
            *(float4*)&As[nb][lrow][lc4 * 4] = pa;
            *(float4*)&Bs[nb][lrow][lc4 * 4] = pb;
            __syncthreads();
        }
    }

#pragma unroll
    for (int i = 0; i < 4; i++)
#pragma unroll
        for (int j = 0; j < 4; j++) {
            U2 a;
            a.u = acc[i][j];
            C[(size_t)(row0 + ty * 4 + i) * N + n0 + tx + j * 16] =
                a.f.x + a.f.y;
        }
}

// ---------------------------------------------------------------------------
// fc partials for one module's state range; one CTA per state.
// ---------------------------------------------------------------------------
__global__ __launch_bounds__(256) void pout_kernel(
    const float* __restrict__ fc_w, int gs0, int m) {
    const int gs = gs0 + blockIdx.x;
    const int warp = threadIdx.x >> 5;
    const int lane = threadIdx.x & 31;
    const int col = m * MSZ + lane * 4;
    const float4 w0 = *(const float4*)(fc_w + col);
    const float4 w1 = *(const float4*)(fc_w + NH + col);
    const float* base = g_traj + (size_t)gs * (NB * MSZ);

    for (int b = warp; b < NB; b += 8) {
        const float4 v = *(const float4*)(base + (size_t)b * MSZ + lane * 4);
        float a0 = v.x * w0.x + v.y * w0.y + v.z * w0.z + v.w * w0.w;
        float a1 = v.x * w1.x + v.y * w1.y + v.z * w1.z + v.w * w1.w;
#pragma unroll
        for (int off = 16; off > 0; off >>= 1) {
            a0 += __shfl_xor_sync(0xffffffffu, a0, off);
            a1 += __shfl_xor_sync(0xffffffffu, a1, off);
        }
        if (lane == 0) {
            g_pout[((size_t)gs * NB + b) * 2 + 0] = a0;
            g_pout[((size_t)gs * NB + b) * 2 + 1] = a1;
        }
    }
}

// ---------------------------------------------------------------------------
// out[b,t,i] = fc_b[i] + sum_m pout[state_of(m,t), b, i]
// ---------------------------------------------------------------------------
__global__ void assemble_kernel(const float* __restrict__ fc_b,
                                float* __restrict__ out) {
    const int idx = blockIdx.x * blockDim.x + threadIdx.x;  // b*512 + t
    const int b = idx >> 9;
    const int t = idx & 511;
    float o0 = fc_b[0];
    float o1 = fc_b[1];
#pragma unroll
    for (int m = 0; m < NMOD; m++) {
        const int gs = c_TOFF[m] + (t >> m) + 1;
        o0 += g_pout[((size_t)gs * NB + b) * 2 + 0];
        o1 += g_pout[((size_t)gs * NB + b) * 2 + 1];
    }
    out[(size_t)idx * 2 + 0] = o0;
    out[(size_t)idx * 2 + 1] = o1;
}

// ---------------------------------------------------------------------------
// Host-side schedule. Two streams:
//   stream0 (default): chain7, U(7,6), chain6, U(6,5), ..., U(1,0), chain0
//   stream1: deferred pieces P(mp, M<=mp-2) + per-module pout, overlapped.
// Events: cEv[mp] = chain mp done; pEv[mp] = first piece of group mp done
// (first piece of group mp is P(mp, mp-2), and all earlier-group pieces
//  targeting mp-2 precede it in stream1, so waiting pEv[mp] before
//  chain (mp-2) covers every deferred piece that chain needs).
// ---------------------------------------------------------------------------
static const int h_TOFF[8] = {0, 513, 770, 899, 964, 997, 1014, 1023};
static const int h_S[8] = {513, 257, 129, 65, 33, 17, 9, 5};

extern "C" void kernel_launch(void* const* d_in, const int* in_sizes, int n_in,
                              void* d_out, int out_size) {
    const float* x     = (const float*)d_in[0];
    const float* W_ih  = (const float*)d_in[1];
    const float* W_hh  = (const float*)d_in[2];
    const float* fc_w  = (const float*)d_in[3];
    const float* fc_b  = (const float*)d_in[4];
    const float* enc_w = (const float*)d_in[5];
    float* out = (float*)d_out;

    static cudaStream_t s1 = nullptr;
    static cudaEvent_t evFork, evJoin, cEv[8], pEv[8];
    if (!s1) {
        cudaStreamCreateWithFlags(&s1, cudaStreamNonBlocking);
        cudaEventCreateWithFlags(&evFork, cudaEventDisableTiming);
        cudaEventCreateWithFlags(&evJoin, cudaEventDisableTiming);
        for (int i = 0; i < 8; i++) {
            cudaEventCreateWithFlags(&cEv[i], cudaEventDisableTiming);
            cudaEventCreateWithFlags(&pEv[i], cudaEventDisableTiming);
        }
    }
    cudaStream_t s0 = 0;

    cudaEventRecord(evFork, s0);
    cudaStreamWaitEvent(s1, evFork, 0);

    // macro-ish helpers
    #define RUN_CHAIN(M)  chain_kernel<M><<<NB, MSZ, 0, s0>>>(x, W_ih, W_hh, enc_w)
    #define URGENT(MP)    g_piece<<<dim3(2 * h_S[MP], 2), 256, 0, s0>>>(W_hh, MP, (MP) - 1)
    #define DEFER(MP, MT) g_piece<<<dim3(2 * h_S[MP], 2), 256, 0, s1>>>(W_hh, MP, MT)
    #define POUT1(M)      pout_kernel<<<h_S[M], 256, 0, s1>>>(fc_w, h_TOFF[M], M)

    RUN_CHAIN(7);  cudaEventRecord(cEv[7], s0);
    URGENT(7);
    // group 7 (deferred)
    cudaStreamWaitEvent(s1, cEv[7], 0);
    DEFER(7, 5);  cudaEventRecord(pEv[7], s1);
    DEFER(7, 4); DEFER(7, 3); DEFER(7, 2); DEFER(7, 1); DEFER(7, 0);
    POUT1(7);

    RUN_CHAIN(6);  cudaEventRecord(cEv[6], s0);
    URGENT(6);
    cudaStreamWaitEvent(s1, cEv[6], 0);
    DEFER(6, 4);  cudaEventRecord(pEv[6], s1);
    DEFER(6, 3); DEFER(6, 2); DEFER(6, 1); DEFER(6, 0);
    POUT1(6);

    cudaStreamWaitEvent(s0, pEv[7], 0);
    RUN_CHAIN(5);  cudaEventRecord(cEv[5], s0);
    URGENT(5);
    cudaStreamWaitEvent(s1, cEv[5], 0);
    DEFER(5, 3);  cudaEventRecord(pEv[5], s1);
    DEFER(5, 2); DEFER(5, 1); DEFER(5, 0);
    POUT1(5);

    cudaStreamWaitEvent(s0, pEv[6], 0);
    RUN_CHAIN(4);  cudaEventRecord(cEv[4], s0);
    URGENT(4);
    cudaStreamWaitEvent(s1, cEv[4], 0);
    DEFER(4, 2);  cudaEventRecord(pEv[4], s1);
    DEFER(4, 1); DEFER(4, 0);
    POUT1(4);

    cudaStreamWaitEvent(s0, pEv[5], 0);
    RUN_CHAIN(3);  cudaEventRecord(cEv[3], s0);
    URGENT(3);
    cudaStreamWaitEvent(s1, cEv[3], 0);
    DEFER(3, 1);  cudaEventRecord(pEv[3], s1);
    DEFER(3, 0);
    POUT1(3);

    cudaStreamWaitEvent(s0, pEv[4], 0);
    RUN_CHAIN(2);  cudaEventRecord(cEv[2], s0);
    URGENT(2);
    cudaStreamWaitEvent(s1, cEv[2], 0);
    DEFER(2, 0);  cudaEventRecord(pEv[2], s1);
    POUT1(2);

    cudaStreamWaitEvent(s0, pEv[3], 0);
    RUN_CHAIN(1);  cudaEventRecord(cEv[1], s0);
    URGENT(1);
    cudaStreamWaitEvent(s1, cEv[1], 0);
    POUT1(1);
    cudaEventRecord(evJoin, s1);

    cudaStreamWaitEvent(s0, pEv[2], 0);
    RUN_CHAIN(0);
    pout_kernel<<<h_S[0], 256, 0, s0>>>(fc_w, h_TOFF[0], 0);

    cudaStreamWaitEvent(s0, evJoin, 0);
    assemble_kernel<<<(NB * NT) / 256, 256, 0, s0>>>(fc_b, out);

    #undef RUN_CHAIN
    #undef URGENT
    #undef DEFER
    #undef POUT1
}